// round 15
// baseline (speedup 1.0000x reference)
#include <cuda_runtime.h>
#include <cuda_bf16.h>
#include <cstdint>

// ---------------------------------------------------------------------------
// MentionScorerGap — R15: R10's overlap structure retried with R12's __stcs
// everywhere (the L2-pollution fix R10 lacked).
//   s2 (fork at t0): copy_kernel -> g_i sections 0,1 (emb copies, stcs)
//   main: asplit, pack, gemm(full), attns, span_attn (S section + scores)
// ---------------------------------------------------------------------------

#define T_TOK  4096
#define D_EMB  768
#define H_HID  150
#define HP     160
#define NC     640
#define L_SPAN 10

#define TM     128
#define TN     64
#define TK     64
#define KPAD   72           // smem row stride in bf16 (144 B)
#define NCHUNK (D_EMB / TK) // 12

#define OFF_AH 0
#define OFF_AL 18432
#define OFF_BH 36864
#define OFF_BL 46080
#define STAGE_BYTES 55296
#define GEMM_SMEM (2 * STAGE_BYTES)   // 110592

__device__ __align__(16) float d_C[(size_t)T_TOK * NC];              // 10.5 MB
__device__ __align__(16) __nv_bfloat16 d_Bh[(size_t)NC * D_EMB];
__device__ __align__(16) __nv_bfloat16 d_Bl[(size_t)NC * D_EMB];
__device__ __align__(16) __nv_bfloat16 d_Ah[(size_t)T_TOK * D_EMB];  // 6.3 MB
__device__ __align__(16) __nv_bfloat16 d_Al[(size_t)T_TOK * D_EMB];
__device__ float d_attns[T_TOK];

// ---- helpers --------------------------------------------------------------
__device__ __forceinline__ uint32_t smem_u32(const void* p) {
    uint32_t a;
    asm("{ .reg .u64 t; cvta.to.shared.u64 t, %1; cvt.u32.u64 %0, t; }"
        : "=r"(a) : "l"(p));
    return a;
}
__device__ __forceinline__ void ldm4(uint32_t* r, uint32_t addr) {
    asm volatile(
        "ldmatrix.sync.aligned.m8n8.x4.shared.b16 {%0,%1,%2,%3}, [%4];"
        : "=r"(r[0]), "=r"(r[1]), "=r"(r[2]), "=r"(r[3]) : "r"(addr));
}
__device__ __forceinline__ void mma16816(float* c, const uint32_t* a,
                                         uint32_t b0, uint32_t b1) {
    asm volatile(
        "mma.sync.aligned.m16n8k16.row.col.f32.bf16.bf16.f32 "
        "{%0,%1,%2,%3}, {%4,%5,%6,%7}, {%8,%9}, {%0,%1,%2,%3};"
        : "+f"(c[0]), "+f"(c[1]), "+f"(c[2]), "+f"(c[3])
        : "r"(a[0]), "r"(a[1]), "r"(a[2]), "r"(a[3]), "r"(b0), "r"(b1));
}
__device__ __forceinline__ void cpasync16(uint32_t saddr, const void* gaddr) {
    asm volatile("cp.async.ca.shared.global [%0], [%1], 16;"
                 :: "r"(saddr), "l"(gaddr));
}
__device__ __forceinline__ uint32_t bf2_hi(float x, float y) {
    __nv_bfloat162 v(__float2bfloat16(x), __float2bfloat16(y));
    return *(uint32_t*)&v;
}
__device__ __forceinline__ uint32_t bf2_lo(float x, float y) {
    float rx = x - __bfloat162float(__float2bfloat16(x));
    float ry = y - __bfloat162float(__float2bfloat16(y));
    __nv_bfloat162 v(__float2bfloat16(rx), __float2bfloat16(ry));
    return *(uint32_t*)&v;
}

// ---------------------------------------------------------------------------
// Kernel 0: split embeds fp32 -> hi/lo bf16 globals
// ---------------------------------------------------------------------------
__global__ __launch_bounds__(256) void asplit_kernel(const float* __restrict__ emb)
{
    int i = blockIdx.x * 256 + threadIdx.x;
    if (i >= T_TOK * D_EMB / 4) return;
    float4 a = ((const float4*)emb)[i];
    ((uint2*)d_Ah)[i] = make_uint2(bf2_hi(a.x, a.y), bf2_hi(a.z, a.w));
    ((uint2*)d_Al)[i] = make_uint2(bf2_lo(a.x, a.y), bf2_lo(a.z, a.w));
}

// ---------------------------------------------------------------------------
// Kernel 1: pack Bt[n][k] = Wcat[k][n] as bf16 hi/lo
// ---------------------------------------------------------------------------
__global__ __launch_bounds__(256) void pack_kernel(
    const float* __restrict__ W_a1, const float* __restrict__ W_m1)
{
    int i = blockIdx.x * 256 + threadIdx.x;
    if (i >= NC * D_EMB) return;
    int n = i / D_EMB, k = i % D_EMB;
    int kb = n / HP, h = n % HP;
    float v = 0.f;
    if (h < H_HID)
        v = (kb == 0) ? W_a1[(size_t)k * H_HID + h]
                      : W_m1[((size_t)(kb - 1) * D_EMB + k) * H_HID + h];
    __nv_bfloat16 hi = __float2bfloat16(v);
    d_Bh[i] = hi;
    d_Bl[i] = __float2bfloat16(v - __bfloat162float(hi));
}

// ---------------------------------------------------------------------------
// Kernel 2: GEMM (R7/R12: TK=64, double-buffered cp.async) — unchanged.
// ---------------------------------------------------------------------------
__device__ __forceinline__ void gemm_stage_load(
    uint32_t sbase, int bm, int bn, int k0, int tid)
{
#pragma unroll
    for (int i = 0; i < 4; i++) {
        int p = tid + i * 256;
        int row = p >> 3, c8 = (p & 7) << 3;
        uint32_t boff = (uint32_t)(row * KPAD + c8) * 2;
        cpasync16(sbase + OFF_AH + boff,
                  d_Ah + (size_t)(bm + row) * D_EMB + k0 + c8);
        cpasync16(sbase + OFF_AL + boff,
                  d_Al + (size_t)(bm + row) * D_EMB + k0 + c8);
    }
#pragma unroll
    for (int i = 0; i < 2; i++) {
        int p = tid + i * 256;
        int row = p >> 3, c8 = (p & 7) << 3;
        uint32_t boff = (uint32_t)(row * KPAD + c8) * 2;
        cpasync16(sbase + OFF_BH + boff,
                  d_Bh + (size_t)(bn + row) * D_EMB + k0 + c8);
        cpasync16(sbase + OFF_BL + boff,
                  d_Bl + (size_t)(bn + row) * D_EMB + k0 + c8);
    }
    asm volatile("cp.async.commit_group;");
}

__global__ __launch_bounds__(256) void gemm_kernel()
{
    extern __shared__ __align__(16) char sm[];
    const int tid = threadIdx.x;
    const int wid = tid >> 5;
    const int lane = tid & 31;
    const int bm = blockIdx.x * TM;
    const int bn = blockIdx.y * TN;
    const int wm = (wid >> 1) * 32;
    const int wn = (wid & 1) * 32;
    const uint32_t smb = smem_u32(sm);

    const int g = lane >> 3;
    const int ro = ((g & 1) << 3) + (lane & 7);
    const int co = (g >> 1) << 3;

    float acc[2][4][4];
#pragma unroll
    for (int mm = 0; mm < 2; mm++)
#pragma unroll
        for (int nn = 0; nn < 4; nn++)
#pragma unroll
            for (int j = 0; j < 4; j++) acc[mm][nn][j] = 0.f;

    gemm_stage_load(smb, bm, bn, 0, tid);

    for (int kc = 0; kc < NCHUNK; kc++) {
        const uint32_t scur = smb + (uint32_t)(kc & 1) * STAGE_BYTES;
        if (kc + 1 < NCHUNK) {
            gemm_stage_load(smb + (uint32_t)((kc + 1) & 1) * STAGE_BYTES,
                            bm, bn, (kc + 1) * TK, tid);
            asm volatile("cp.async.wait_group 1;");
        } else {
            asm volatile("cp.async.wait_group 0;");
        }
        __syncthreads();

#pragma unroll
        for (int kk = 0; kk < 4; kk++) {
            const int k16 = kk * 16;
            uint32_t ah[2][4], al[2][4], bh[2][4], bl[2][4];
#pragma unroll
            for (int mm = 0; mm < 2; mm++) {
                uint32_t adr = scur + OFF_AH +
                    (uint32_t)((wm + mm * 16 + ro) * KPAD + k16 + co) * 2;
                ldm4(ah[mm], adr);
                ldm4(al[mm], adr + (OFF_AL - OFF_AH));
            }
#pragma unroll
            for (int bb = 0; bb < 2; bb++) {
                uint32_t adr = scur + OFF_BH +
                    (uint32_t)((wn + bb * 16 + ro) * KPAD + k16 + co) * 2;
                ldm4(bh[bb], adr);
                ldm4(bl[bb], adr + (OFF_BL - OFF_BH));
            }
#pragma unroll
            for (int mm = 0; mm < 2; mm++)
#pragma unroll
                for (int nn = 0; nn < 4; nn++) {
                    uint32_t b0h = bh[nn >> 1][nn & 1];
                    uint32_t b1h = bh[nn >> 1][(nn & 1) + 2];
                    uint32_t b0l = bl[nn >> 1][nn & 1];
                    uint32_t b1l = bl[nn >> 1][(nn & 1) + 2];
                    mma16816(acc[mm][nn], ah[mm], b0h, b1h);
                    mma16816(acc[mm][nn], ah[mm], b0l, b1l);
                    mma16816(acc[mm][nn], al[mm], b0h, b1h);
                }
        }
        __syncthreads();
    }

    const int cr = lane >> 2;
    const int cc = (lane & 3) << 1;
#pragma unroll
    for (int mm = 0; mm < 2; mm++)
#pragma unroll
        for (int nn = 0; nn < 4; nn++) {
            int row = bm + wm + mm * 16 + cr;
            int col = bn + wn + nn * 8 + cc;
            *(float2*)&d_C[(size_t)row * NC + col] =
                make_float2(acc[mm][nn][0], acc[mm][nn][1]);
            *(float2*)&d_C[(size_t)(row + 8) * NC + col] =
                make_float2(acc[mm][nn][2], acc[mm][nn][3]);
        }
}

// ---------------------------------------------------------------------------
// Kernel 3: per-token attention logit
// ---------------------------------------------------------------------------
__global__ __launch_bounds__(256) void attns_kernel(
    const float* __restrict__ b_a1, const float* __restrict__ W_a2,
    const float* __restrict__ b_a2)
{
    int t = blockIdx.x * 8 + (threadIdx.x >> 5);
    int lane = threadIdx.x & 31;
    if (t >= T_TOK) return;
    float p = 0.f;
    for (int h = lane; h < H_HID; h += 32)
        p = fmaf(fmaxf(d_C[(size_t)t * NC + h] + b_a1[h], 0.f), W_a2[h], p);
#pragma unroll
    for (int o = 16; o; o >>= 1) p += __shfl_xor_sync(0xffffffffu, p, o);
    if (lane == 0) d_attns[t] = p + b_a2[0];
}

// ---------------------------------------------------------------------------
// Kernel 4 (side stream): emb-copy 2/3 of g_i. CTA per token, 128 threads,
// float2 units, __stcs (evict-first: don't pollute L2 under the GEMM).
// ---------------------------------------------------------------------------
__global__ __launch_bounds__(128) void copy_kernel(
    const float* __restrict__ emb, float* __restrict__ g)
{
    const int t = blockIdx.x;
    const int tid = threadIdx.x;
    const int lmax = min(L_SPAN - 1, T_TOK - 1 - t);

    const float2* et2 = (const float2*)(emb + (size_t)t * D_EMB);
    float2 st2[3];
#pragma unroll
    for (int c = 0; c < 3; c++) st2[c] = et2[tid + 128 * c];

    for (int l = 0; l < L_SPAN; l++) {
        const int e = t + min(l, lmax);
        float2* gout2 = (float2*)(g + (size_t)(t * L_SPAN + l) * (3 * D_EMB));
        const float2* ee2 = (const float2*)(emb + (size_t)e * D_EMB);
#pragma unroll
        for (int c = 0; c < 3; c++) {
            const int idx = tid + 128 * c;
            __stcs(&gout2[idx], st2[c]);
            __stcs(&gout2[384 + idx], ee2[idx]);
        }
    }
}

// ---------------------------------------------------------------------------
// Kernel 5: attn-weighted third of g_i + mention scores. CTA per token,
// 128 threads, __stcs (R12 inner loop minus the two copy sections).
// ---------------------------------------------------------------------------
__global__ __launch_bounds__(128) void span_attn_kernel(
    const float* __restrict__ emb,
    const float* __restrict__ b_m1, const float* __restrict__ W_m2,
    const float* __restrict__ b_m2,
    float* __restrict__ g, float* __restrict__ scores)
{
    __shared__ float s_u[L_SPAN];
    __shared__ float s_rZ[L_SPAN];

    const int t = blockIdx.x;
    const int tid = threadIdx.x;
    const int lmax = min(L_SPAN - 1, T_TOK - 1 - t);

    if (tid == 0) {
        float a[L_SPAN];
        float mx = -3.4e38f;
#pragma unroll
        for (int j = 0; j < L_SPAN; j++) {
            a[j] = (j <= lmax) ? d_attns[t + j] : -3.4e38f;
            mx = fmaxf(mx, a[j]);
        }
        float Z = 0.f;
#pragma unroll
        for (int j = 0; j < L_SPAN; j++) {
            float uu = (j <= lmax) ? __expf(a[j] - mx) : 0.f;
            s_u[j] = uu;
            Z += uu;
            s_rZ[j] = __frcp_rn(Z);
        }
    }
    __syncthreads();

    // ---- mention scores (warp 0; registers die before the store loop) ----
    if (tid < 32) {
        const int lane = tid;
        float ps[5], b1[5], w2[5], paacc[5];
#pragma unroll
        for (int k = 0; k < 5; k++) {
            int h = lane + 32 * k;
            bool ok = h < H_HID;
            ps[k]    = d_C[(size_t)t * NC + HP + h];
            b1[k]    = ok ? b_m1[h] : 0.f;
            w2[k]    = ok ? W_m2[h] : 0.f;
            paacc[k] = 0.f;
        }
        const float bm2 = b_m2[0];
        for (int l = 0; l < L_SPAN; l++) {
            if (l <= lmax) {
                float uu = s_u[l];
                const float* pr = d_C + (size_t)(t + l) * NC + 3 * HP;
#pragma unroll
                for (int k = 0; k < 5; k++)
                    paacc[k] = fmaf(uu, pr[lane + 32 * k], paacc[k]);
            }
            const int e = t + min(l, lmax);
            const float rZ = s_rZ[l];
            const float* per = d_C + (size_t)e * NC + 2 * HP;
            float partial = 0.f;
#pragma unroll
            for (int k = 0; k < 5; k++) {
                int h = lane + 32 * k;
                if (h < H_HID) {
                    float hid = ps[k] + per[h] + paacc[k] * rZ + b1[k];
                    partial = fmaf(fmaxf(hid, 0.f), w2[k], partial);
                }
            }
#pragma unroll
            for (int o = 16; o; o >>= 1)
                partial += __shfl_xor_sync(0xffffffffu, partial, o);
            if (lane == 0) scores[(size_t)t * L_SPAN + l] = partial + bm2;
        }
    }

    // ---- attn-weighted section stores ----
    float2 S2[3];
#pragma unroll
    for (int c = 0; c < 3; c++) S2[c] = make_float2(0.f, 0.f);

    for (int l = 0; l < L_SPAN; l++) {
        if (l <= lmax) {
            const float uu = s_u[l];
            const float2* er2 = (const float2*)(emb + (size_t)(t + l) * D_EMB);
#pragma unroll
            for (int c = 0; c < 3; c++) {
                float2 v = er2[tid + 128 * c];
                S2[c].x = fmaf(uu, v.x, S2[c].x);
                S2[c].y = fmaf(uu, v.y, S2[c].y);
            }
        }
        const float rZ = s_rZ[l];
        float2* gout2 = (float2*)(g + (size_t)(t * L_SPAN + l) * (3 * D_EMB));
#pragma unroll
        for (int c = 0; c < 3; c++) {
            const int idx = tid + 128 * c;
            __stcs(&gout2[768 + idx], make_float2(S2[c].x * rZ, S2[c].y * rZ));
        }
    }
}

// ---------------------------------------------------------------------------
extern "C" void kernel_launch(void* const* d_in, const int* in_sizes, int n_in,
                              void* d_out, int out_size) {
    const float* emb  = (const float*)d_in[0];
    // d_in[1] span_starts, d_in[2] span_ends: analytic structure (t*L + l).
    const float* W_a1 = (const float*)d_in[3];
    const float* b_a1 = (const float*)d_in[4];
    const float* W_a2 = (const float*)d_in[5];
    const float* b_a2 = (const float*)d_in[6];
    const float* W_m1 = (const float*)d_in[7];
    const float* b_m1 = (const float*)d_in[8];
    const float* W_m2 = (const float*)d_in[9];
    const float* b_m2 = (const float*)d_in[10];

    float* out = (float*)d_out;
    float* g_i = out;                                         // [N, 3D]
    float* scores = out + (size_t)T_TOK * L_SPAN * 3 * D_EMB; // [N]

    static cudaStream_t s2 = nullptr;
    static cudaEvent_t evFork = nullptr, evJoin = nullptr;
    if (!s2) {
        cudaFuncSetAttribute(gemm_kernel,
                             cudaFuncAttributeMaxDynamicSharedMemorySize,
                             GEMM_SMEM);
        cudaStreamCreateWithFlags(&s2, cudaStreamNonBlocking);
        cudaEventCreateWithFlags(&evFork, cudaEventDisableTiming);
        cudaEventCreateWithFlags(&evJoin, cudaEventDisableTiming);
    }

    // fork at t0: emb->g_i copies depend only on the input
    cudaEventRecord(evFork, 0);
    cudaStreamWaitEvent(s2, evFork, 0);
    copy_kernel<<<T_TOK, 128, 0, s2>>>(emb, g_i);
    cudaEventRecord(evJoin, s2);

    asplit_kernel<<<(T_TOK * D_EMB / 4 + 255) / 256, 256>>>(emb);
    pack_kernel<<<(NC * D_EMB + 255) / 256, 256>>>(W_a1, W_m1);
    gemm_kernel<<<dim3(T_TOK / TM, NC / TN), 256, GEMM_SMEM>>>();
    attns_kernel<<<T_TOK / 8, 256>>>(b_a1, W_a2, b_a2);
    span_attn_kernel<<<T_TOK, 128>>>(emb, b_m1, W_m2, b_m2, g_i, scores);

    cudaStreamWaitEvent(0, evJoin, 0);
}

// round 16
// speedup vs baseline: 1.0428x; 1.0428x over previous
#include <cuda_runtime.h>
#include <cuda_bf16.h>
#include <cstdint>

// ---------------------------------------------------------------------------
// MentionScorerGap — R16: R12 (best, 132.7us) + ONE change: the GEMM
// mainloop double-buffers ldmatrix fragments across k16 steps (prefetch
// kk+1's fragments before issuing kk's MMAs) to hide LDSM latency.
// ---------------------------------------------------------------------------

#define T_TOK  4096
#define D_EMB  768
#define H_HID  150
#define HP     160
#define NC     640
#define L_SPAN 10

#define TM     128
#define TN     64
#define TK     64
#define KPAD   72           // smem row stride in bf16 (144 B)
#define NCHUNK (D_EMB / TK) // 12

#define OFF_AH 0
#define OFF_AL 18432
#define OFF_BH 36864
#define OFF_BL 46080
#define STAGE_BYTES 55296
#define GEMM_SMEM (2 * STAGE_BYTES)   // 110592

__device__ __align__(16) float d_C[(size_t)T_TOK * NC];              // 10.5 MB
__device__ __align__(16) __nv_bfloat16 d_Bh[(size_t)NC * D_EMB];
__device__ __align__(16) __nv_bfloat16 d_Bl[(size_t)NC * D_EMB];
__device__ __align__(16) __nv_bfloat16 d_Ah[(size_t)T_TOK * D_EMB];  // 6.3 MB
__device__ __align__(16) __nv_bfloat16 d_Al[(size_t)T_TOK * D_EMB];
__device__ float d_attns[T_TOK];

// ---- helpers --------------------------------------------------------------
__device__ __forceinline__ uint32_t smem_u32(const void* p) {
    uint32_t a;
    asm("{ .reg .u64 t; cvta.to.shared.u64 t, %1; cvt.u32.u64 %0, t; }"
        : "=r"(a) : "l"(p));
    return a;
}
__device__ __forceinline__ void ldm4(uint32_t* r, uint32_t addr) {
    asm volatile(
        "ldmatrix.sync.aligned.m8n8.x4.shared.b16 {%0,%1,%2,%3}, [%4];"
        : "=r"(r[0]), "=r"(r[1]), "=r"(r[2]), "=r"(r[3]) : "r"(addr));
}
__device__ __forceinline__ void mma16816(float* c, const uint32_t* a,
                                         uint32_t b0, uint32_t b1) {
    asm volatile(
        "mma.sync.aligned.m16n8k16.row.col.f32.bf16.bf16.f32 "
        "{%0,%1,%2,%3}, {%4,%5,%6,%7}, {%8,%9}, {%0,%1,%2,%3};"
        : "+f"(c[0]), "+f"(c[1]), "+f"(c[2]), "+f"(c[3])
        : "r"(a[0]), "r"(a[1]), "r"(a[2]), "r"(a[3]), "r"(b0), "r"(b1));
}
__device__ __forceinline__ void cpasync16(uint32_t saddr, const void* gaddr) {
    asm volatile("cp.async.ca.shared.global [%0], [%1], 16;"
                 :: "r"(saddr), "l"(gaddr));
}
__device__ __forceinline__ uint32_t bf2_hi(float x, float y) {
    __nv_bfloat162 v(__float2bfloat16(x), __float2bfloat16(y));
    return *(uint32_t*)&v;
}
__device__ __forceinline__ uint32_t bf2_lo(float x, float y) {
    float rx = x - __bfloat162float(__float2bfloat16(x));
    float ry = y - __bfloat162float(__float2bfloat16(y));
    __nv_bfloat162 v(__float2bfloat16(rx), __float2bfloat16(ry));
    return *(uint32_t*)&v;
}

// ---------------------------------------------------------------------------
// Kernel 0: split embeds fp32 -> hi/lo bf16 globals
// ---------------------------------------------------------------------------
__global__ __launch_bounds__(256) void asplit_kernel(const float* __restrict__ emb)
{
    int i = blockIdx.x * 256 + threadIdx.x;
    if (i >= T_TOK * D_EMB / 4) return;
    float4 a = ((const float4*)emb)[i];
    ((uint2*)d_Ah)[i] = make_uint2(bf2_hi(a.x, a.y), bf2_hi(a.z, a.w));
    ((uint2*)d_Al)[i] = make_uint2(bf2_lo(a.x, a.y), bf2_lo(a.z, a.w));
}

// ---------------------------------------------------------------------------
// Kernel 1: pack Bt[n][k] = Wcat[k][n] as bf16 hi/lo
// ---------------------------------------------------------------------------
__global__ __launch_bounds__(256) void pack_kernel(
    const float* __restrict__ W_a1, const float* __restrict__ W_m1)
{
    int i = blockIdx.x * 256 + threadIdx.x;
    if (i >= NC * D_EMB) return;
    int n = i / D_EMB, k = i % D_EMB;
    int kb = n / HP, h = n % HP;
    float v = 0.f;
    if (h < H_HID)
        v = (kb == 0) ? W_a1[(size_t)k * H_HID + h]
                      : W_m1[((size_t)(kb - 1) * D_EMB + k) * H_HID + h];
    __nv_bfloat16 hi = __float2bfloat16(v);
    d_Bh[i] = hi;
    d_Bl[i] = __float2bfloat16(v - __bfloat162float(hi));
}

// ---------------------------------------------------------------------------
// Kernel 2: GEMM — TK=64 double-buffered cp.async (R12), PLUS fragment
// double-buffering across the 4 k16 steps.
// ---------------------------------------------------------------------------
__device__ __forceinline__ void gemm_stage_load(
    uint32_t sbase, int bm, int bn, int k0, int tid)
{
#pragma unroll
    for (int i = 0; i < 4; i++) {
        int p = tid + i * 256;
        int row = p >> 3, c8 = (p & 7) << 3;
        uint32_t boff = (uint32_t)(row * KPAD + c8) * 2;
        cpasync16(sbase + OFF_AH + boff,
                  d_Ah + (size_t)(bm + row) * D_EMB + k0 + c8);
        cpasync16(sbase + OFF_AL + boff,
                  d_Al + (size_t)(bm + row) * D_EMB + k0 + c8);
    }
#pragma unroll
    for (int i = 0; i < 2; i++) {
        int p = tid + i * 256;
        int row = p >> 3, c8 = (p & 7) << 3;
        uint32_t boff = (uint32_t)(row * KPAD + c8) * 2;
        cpasync16(sbase + OFF_BH + boff,
                  d_Bh + (size_t)(bn + row) * D_EMB + k0 + c8);
        cpasync16(sbase + OFF_BL + boff,
                  d_Bl + (size_t)(bn + row) * D_EMB + k0 + c8);
    }
    asm volatile("cp.async.commit_group;");
}

__global__ __launch_bounds__(256) void gemm_kernel()
{
    extern __shared__ __align__(16) char sm[];
    const int tid = threadIdx.x;
    const int wid = tid >> 5;
    const int lane = tid & 31;
    const int bm = blockIdx.x * TM;
    const int bn = blockIdx.y * TN;
    const int wm = (wid >> 1) * 32;
    const int wn = (wid & 1) * 32;
    const uint32_t smb = smem_u32(sm);

    const int g = lane >> 3;
    const int ro = ((g & 1) << 3) + (lane & 7);
    const int co = (g >> 1) << 3;

    float acc[2][4][4];
#pragma unroll
    for (int mm = 0; mm < 2; mm++)
#pragma unroll
        for (int nn = 0; nn < 4; nn++)
#pragma unroll
            for (int j = 0; j < 4; j++) acc[mm][nn][j] = 0.f;

    // fragment double buffers
    uint32_t ah[2][2][4], al[2][2][4], bh[2][2][4], bl[2][2][4];

    gemm_stage_load(smb, bm, bn, 0, tid);

    for (int kc = 0; kc < NCHUNK; kc++) {
        const uint32_t scur = smb + (uint32_t)(kc & 1) * STAGE_BYTES;
        if (kc + 1 < NCHUNK) {
            gemm_stage_load(smb + (uint32_t)((kc + 1) & 1) * STAGE_BYTES,
                            bm, bn, (kc + 1) * TK, tid);
            asm volatile("cp.async.wait_group 1;");
        } else {
            asm volatile("cp.async.wait_group 0;");
        }
        __syncthreads();

        // prologue: fragments for k16 step 0 -> buffer 0
#pragma unroll
        for (int mm = 0; mm < 2; mm++) {
            uint32_t adr = scur + OFF_AH +
                (uint32_t)((wm + mm * 16 + ro) * KPAD + co) * 2;
            ldm4(ah[0][mm], adr);
            ldm4(al[0][mm], adr + (OFF_AL - OFF_AH));
        }
#pragma unroll
        for (int bb = 0; bb < 2; bb++) {
            uint32_t adr = scur + OFF_BH +
                (uint32_t)((wn + bb * 16 + ro) * KPAD + co) * 2;
            ldm4(bh[0][bb], adr);
            ldm4(bl[0][bb], adr + (OFF_BL - OFF_BH));
        }

#pragma unroll
        for (int kk = 0; kk < 4; kk++) {
            const int cur = kk & 1;
            // prefetch next k16 step's fragments into the other buffer
            if (kk < 3) {
                const int nxt = cur ^ 1;
                const int k16n = (kk + 1) * 16;
#pragma unroll
                for (int mm = 0; mm < 2; mm++) {
                    uint32_t adr = scur + OFF_AH +
                        (uint32_t)((wm + mm * 16 + ro) * KPAD + k16n + co) * 2;
                    ldm4(ah[nxt][mm], adr);
                    ldm4(al[nxt][mm], adr + (OFF_AL - OFF_AH));
                }
#pragma unroll
                for (int bb = 0; bb < 2; bb++) {
                    uint32_t adr = scur + OFF_BH +
                        (uint32_t)((wn + bb * 16 + ro) * KPAD + k16n + co) * 2;
                    ldm4(bh[nxt][bb], adr);
                    ldm4(bl[nxt][bb], adr + (OFF_BL - OFF_BH));
                }
            }
            // MMAs for the current buffer
#pragma unroll
            for (int mm = 0; mm < 2; mm++)
#pragma unroll
                for (int nn = 0; nn < 4; nn++) {
                    uint32_t b0h = bh[cur][nn >> 1][nn & 1];
                    uint32_t b1h = bh[cur][nn >> 1][(nn & 1) + 2];
                    uint32_t b0l = bl[cur][nn >> 1][nn & 1];
                    uint32_t b1l = bl[cur][nn >> 1][(nn & 1) + 2];
                    mma16816(acc[mm][nn], ah[cur][mm], b0h, b1h);
                    mma16816(acc[mm][nn], ah[cur][mm], b0l, b1l);
                    mma16816(acc[mm][nn], al[cur][mm], b0h, b1h);
                }
        }
        __syncthreads();
    }

    const int cr = lane >> 2;
    const int cc = (lane & 3) << 1;
#pragma unroll
    for (int mm = 0; mm < 2; mm++)
#pragma unroll
        for (int nn = 0; nn < 4; nn++) {
            int row = bm + wm + mm * 16 + cr;
            int col = bn + wn + nn * 8 + cc;
            *(float2*)&d_C[(size_t)row * NC + col] =
                make_float2(acc[mm][nn][0], acc[mm][nn][1]);
            *(float2*)&d_C[(size_t)(row + 8) * NC + col] =
                make_float2(acc[mm][nn][2], acc[mm][nn][3]);
        }
}

// ---------------------------------------------------------------------------
// Kernel 3: per-token attention logit
// ---------------------------------------------------------------------------
__global__ __launch_bounds__(256) void attns_kernel(
    const float* __restrict__ b_a1, const float* __restrict__ W_a2,
    const float* __restrict__ b_a2)
{
    int t = blockIdx.x * 8 + (threadIdx.x >> 5);
    int lane = threadIdx.x & 31;
    if (t >= T_TOK) return;
    float p = 0.f;
    for (int h = lane; h < H_HID; h += 32)
        p = fmaf(fmaxf(d_C[(size_t)t * NC + h] + b_a1[h], 0.f), W_a2[h], p);
#pragma unroll
    for (int o = 16; o; o >>= 1) p += __shfl_xor_sync(0xffffffffu, p, o);
    if (lane == 0) d_attns[t] = p + b_a2[0];
}

// ---------------------------------------------------------------------------
// Kernel 4: span kernel (R12, measured-best) — CTA per token, 128 threads,
// float2 units, __stcs streaming stores, scores in warp 0.
// ---------------------------------------------------------------------------
__global__ __launch_bounds__(128) void span_kernel(
    const float* __restrict__ emb,
    const float* __restrict__ b_m1, const float* __restrict__ W_m2,
    const float* __restrict__ b_m2,
    float* __restrict__ g, float* __restrict__ scores)
{
    __shared__ float s_u[L_SPAN];
    __shared__ float s_rZ[L_SPAN];

    const int t = blockIdx.x;
    const int tid = threadIdx.x;
    const int lmax = min(L_SPAN - 1, T_TOK - 1 - t);

    if (tid == 0) {
        float a[L_SPAN];
        float mx = -3.4e38f;
#pragma unroll
        for (int j = 0; j < L_SPAN; j++) {
            a[j] = (j <= lmax) ? d_attns[t + j] : -3.4e38f;
            mx = fmaxf(mx, a[j]);
        }
        float Z = 0.f;
#pragma unroll
        for (int j = 0; j < L_SPAN; j++) {
            float uu = (j <= lmax) ? __expf(a[j] - mx) : 0.f;
            s_u[j] = uu;
            Z += uu;
            s_rZ[j] = __frcp_rn(Z);
        }
    }
    __syncthreads();

    if (tid < 32) {
        const int lane = tid;
        float ps[5], b1[5], w2[5], paacc[5];
#pragma unroll
        for (int k = 0; k < 5; k++) {
            int h = lane + 32 * k;
            bool ok = h < H_HID;
            ps[k]    = d_C[(size_t)t * NC + HP + h];
            b1[k]    = ok ? b_m1[h] : 0.f;
            w2[k]    = ok ? W_m2[h] : 0.f;
            paacc[k] = 0.f;
        }
        const float bm2 = b_m2[0];
        for (int l = 0; l < L_SPAN; l++) {
            if (l <= lmax) {
                float uu = s_u[l];
                const float* pr = d_C + (size_t)(t + l) * NC + 3 * HP;
#pragma unroll
                for (int k = 0; k < 5; k++)
                    paacc[k] = fmaf(uu, pr[lane + 32 * k], paacc[k]);
            }
            const int e = t + min(l, lmax);
            const float rZ = s_rZ[l];
            const float* per = d_C + (size_t)e * NC + 2 * HP;
            float partial = 0.f;
#pragma unroll
            for (int k = 0; k < 5; k++) {
                int h = lane + 32 * k;
                if (h < H_HID) {
                    float hid = ps[k] + per[h] + paacc[k] * rZ + b1[k];
                    partial = fmaf(fmaxf(hid, 0.f), w2[k], partial);
                }
            }
#pragma unroll
            for (int o = 16; o; o >>= 1)
                partial += __shfl_xor_sync(0xffffffffu, partial, o);
            if (lane == 0) scores[(size_t)t * L_SPAN + l] = partial + bm2;
        }
    }

    const float2* et2 = (const float2*)(emb + (size_t)t * D_EMB);
    float2 st2[3], S2[3];
#pragma unroll
    for (int c = 0; c < 3; c++) {
        st2[c] = et2[tid + 128 * c];
        S2[c] = make_float2(0.f, 0.f);
    }

    for (int l = 0; l < L_SPAN; l++) {
        if (l <= lmax) {
            const float uu = s_u[l];
            const float2* er2 = (const float2*)(emb + (size_t)(t + l) * D_EMB);
#pragma unroll
            for (int c = 0; c < 3; c++) {
                float2 v = er2[tid + 128 * c];
                S2[c].x = fmaf(uu, v.x, S2[c].x);
                S2[c].y = fmaf(uu, v.y, S2[c].y);
            }
        }
        const int e = t + min(l, lmax);
        const float rZ = s_rZ[l];

        float2* gout2 = (float2*)(g + (size_t)(t * L_SPAN + l) * (3 * D_EMB));
        const float2* ee2 = (const float2*)(emb + (size_t)e * D_EMB);
#pragma unroll
        for (int c = 0; c < 3; c++) {
            const int idx = tid + 128 * c;
            __stcs(&gout2[idx], st2[c]);
            __stcs(&gout2[384 + idx], ee2[idx]);
            __stcs(&gout2[768 + idx], make_float2(S2[c].x * rZ, S2[c].y * rZ));
        }
    }
}

// ---------------------------------------------------------------------------
extern "C" void kernel_launch(void* const* d_in, const int* in_sizes, int n_in,
                              void* d_out, int out_size) {
    const float* emb  = (const float*)d_in[0];
    // d_in[1] span_starts, d_in[2] span_ends: analytic structure (t*L + l).
    const float* W_a1 = (const float*)d_in[3];
    const float* b_a1 = (const float*)d_in[4];
    const float* W_a2 = (const float*)d_in[5];
    const float* b_a2 = (const float*)d_in[6];
    const float* W_m1 = (const float*)d_in[7];
    const float* b_m1 = (const float*)d_in[8];
    const float* W_m2 = (const float*)d_in[9];
    const float* b_m2 = (const float*)d_in[10];

    float* out = (float*)d_out;
    float* g_i = out;                                         // [N, 3D]
    float* scores = out + (size_t)T_TOK * L_SPAN * 3 * D_EMB; // [N]

    static int smem_set = 0;
    if (!smem_set) {
        cudaFuncSetAttribute(gemm_kernel,
                             cudaFuncAttributeMaxDynamicSharedMemorySize,
                             GEMM_SMEM);
        smem_set = 1;
    }

    asplit_kernel<<<(T_TOK * D_EMB / 4 + 255) / 256, 256>>>(emb);
    pack_kernel<<<(NC * D_EMB + 255) / 256, 256>>>(W_a1, W_m1);
    gemm_kernel<<<dim3(T_TOK / TM, NC / TN), 256, GEMM_SMEM>>>();
    attns_kernel<<<T_TOK / 8, 256>>>(b_a1, W_a2, b_a2);
    span_kernel<<<T_TOK, 128>>>(emb, b_m1, W_m2, b_m2, g_i, scores);
}